// round 1
// baseline (speedup 1.0000x reference)
#include <cuda_runtime.h>
#include <math.h>

// Problem constants
#define B_  2
#define L_  2048
#define D_  1024
#define H_  16
#define HD  64
#define M_  (B_ * L_)   // 4096

// ---------------------------------------------------------------------------
// Scratch (static device globals; no dynamic allocation allowed)
// ---------------------------------------------------------------------------
__device__ float g_q[M_ * D_];
__device__ float g_k[M_ * D_];
__device__ float g_v[M_ * D_];
__device__ float g_y[M_ * D_];

// ---------------------------------------------------------------------------
// SGEMM: C[M,N] = alpha * A[M,K] @ B[K,N]
// Block tile 128x128, K-tile 8, 256 threads, 8x8 micro-tile per thread.
// M,N,K all multiples of tile sizes here (4096/1024/1024) -> no bounds checks.
// ---------------------------------------------------------------------------
__global__ __launch_bounds__(256) void sgemm128(
    const float* __restrict__ A, const float* __restrict__ Bm,
    float* __restrict__ C, int M, int N, int K, float alpha)
{
    __shared__ float As[8][128];   // A transposed: As[k][m]
    __shared__ float Bs[8][128];   // Bs[k][n]

    const int tid = threadIdx.x;
    const int bm = blockIdx.y * 128;
    const int bn = blockIdx.x * 128;
    const int ty = tid >> 4;       // 0..15
    const int tx = tid & 15;       // 0..15

    float acc[8][8];
#pragma unroll
    for (int i = 0; i < 8; ++i)
#pragma unroll
        for (int j = 0; j < 8; ++j) acc[i][j] = 0.0f;

    const int a_row = tid >> 1;          // 0..127
    const int a_k   = (tid & 1) * 4;     // 0 or 4
    const int b_k   = tid >> 5;          // 0..7
    const int b_col = (tid & 31) * 4;    // 0..124

    const float* Ap = A  + (size_t)(bm + a_row) * K + a_k;
    const float* Bp = Bm + (size_t)b_k * N + bn + b_col;

    for (int k0 = 0; k0 < K; k0 += 8) {
        float4 av = *(const float4*)Ap;
        float4 bv = *(const float4*)Bp;
        __syncthreads();   // previous compute done before overwriting smem
        As[a_k + 0][a_row] = av.x;
        As[a_k + 1][a_row] = av.y;
        As[a_k + 2][a_row] = av.z;
        As[a_k + 3][a_row] = av.w;
        *(float4*)&Bs[b_k][b_col] = bv;
        __syncthreads();

#pragma unroll
        for (int kk = 0; kk < 8; ++kk) {
            float4 a0 = *(const float4*)&As[kk][ty * 8];
            float4 a1 = *(const float4*)&As[kk][ty * 8 + 4];
            float4 b0 = *(const float4*)&Bs[kk][tx * 8];
            float4 b1 = *(const float4*)&Bs[kk][tx * 8 + 4];
            float ar[8] = {a0.x, a0.y, a0.z, a0.w, a1.x, a1.y, a1.z, a1.w};
            float br[8] = {b0.x, b0.y, b0.z, b0.w, b1.x, b1.y, b1.z, b1.w};
#pragma unroll
            for (int i = 0; i < 8; ++i)
#pragma unroll
                for (int j = 0; j < 8; ++j)
                    acc[i][j] = fmaf(ar[i], br[j], acc[i][j]);
        }
        Ap += 8;
        Bp += (size_t)8 * N;
    }

    // epilogue
#pragma unroll
    for (int i = 0; i < 8; ++i) {
        float* crow = C + (size_t)(bm + ty * 8 + i) * N + bn + tx * 8;
        float4 o0 = make_float4(alpha * acc[i][0], alpha * acc[i][1],
                                alpha * acc[i][2], alpha * acc[i][3]);
        float4 o1 = make_float4(alpha * acc[i][4], alpha * acc[i][5],
                                alpha * acc[i][6], alpha * acc[i][7]);
        *(float4*)(crow)     = o0;
        *(float4*)(crow + 4) = o1;
    }
}

// ---------------------------------------------------------------------------
// RoPE applied in-place to q and k (layout [b*l][d], head = 64-col slice)
// angle(pos, i) = pos * 10000^(-2i/64),  pairs (2i, 2i+1) within each head.
// ---------------------------------------------------------------------------
__global__ __launch_bounds__(256) void rope_kernel(float* __restrict__ q,
                                                   float* __restrict__ k)
{
    int idx = blockIdx.x * blockDim.x + threadIdx.x;   // < M_ * 512
    int row = idx >> 9;          // b*L + l
    int c   = idx & 511;
    int h   = c >> 5;            // head
    int i   = c & 31;            // pair index 0..31
    int pos = row & (L_ - 1);    // l  (L_ = 2048 power of 2)

    // inv_freq = 10000^(-2i/64) = 2^(-log2(10000) * 2i/64)
    float freq = exp2f(-13.287712379549449f * (float)(2 * i) * (1.0f / 64.0f));
    float ang  = (float)pos * freq;
    float s, cc;
    sincosf(ang, &s, &cc);

    int base = row * D_ + h * HD + 2 * i;
    float q0 = q[base], q1 = q[base + 1];
    q[base]     = q0 * cc - q1 * s;
    q[base + 1] = q1 * cc + q0 * s;
    float k0 = k[base], k1 = k[base + 1];
    k[base]     = k0 * cc - k1 * s;
    k[base + 1] = k1 * cc + k0 * s;
}

// ---------------------------------------------------------------------------
// Flash attention (fp32): per (b, h, q-tile of 64) block.
// Bq = Bk = 64, head dim 64, 256 threads, 4x4 micro-tiles.
// Smem: Qs^T [64][65], K^T/P shared buffer [64][65], Vs [64][64].
// Online softmax over 32 key tiles. q is pre-scaled by 1/sqrt(d).
// ---------------------------------------------------------------------------
#define FA_SMEM_FLOATS (64 * 65 * 2 + 64 * 64)
#define FA_SMEM_BYTES  (FA_SMEM_FLOATS * 4)

__global__ __launch_bounds__(256) void flash_kernel(
    const float* __restrict__ q, const float* __restrict__ k,
    const float* __restrict__ v, float* __restrict__ o)
{
    extern __shared__ float sm[];
    float* Qs  = sm;                 // [kk][row], stride 65
    float* KPs = sm + 64 * 65;       // K: [kk][key] stride 65; later P: [row][key] stride 65
    float* Vs  = sm + 2 * 64 * 65;   // [key][c], stride 64

    const int tid = threadIdx.x;
    const int ty = tid >> 4;   // 0..15 -> query rows ty*4..ty*4+3
    const int tx = tid & 15;   // 0..15 -> key cols / hd cols tx*4..tx*4+3
    const int q0 = blockIdx.x * 64;
    const int h  = blockIdx.y;
    const int b  = blockIdx.z;

    const float* qb = q + ((size_t)b * L_ + q0) * D_ + h * HD;
    const float* kb = k + (size_t)b * L_ * D_ + h * HD;
    const float* vb = v + (size_t)b * L_ * D_ + h * HD;

    // Load Q tile transposed: Qs[kk][row]
#pragma unroll
    for (int it = 0; it < 4; ++it) {
        int idx = tid + it * 256;        // 0..1023
        int r  = idx >> 4;               // 0..63
        int c4 = idx & 15;               // 0..15
        float4 val = *(const float4*)(qb + (size_t)r * D_ + c4 * 4);
        Qs[(c4 * 4 + 0) * 65 + r] = val.x;
        Qs[(c4 * 4 + 1) * 65 + r] = val.y;
        Qs[(c4 * 4 + 2) * 65 + r] = val.z;
        Qs[(c4 * 4 + 3) * 65 + r] = val.w;
    }

    float acc[4][4];
#pragma unroll
    for (int i = 0; i < 4; ++i)
#pragma unroll
        for (int j = 0; j < 4; ++j) acc[i][j] = 0.0f;
    float mrow[4], lrow[4];
#pragma unroll
    for (int i = 0; i < 4; ++i) { mrow[i] = -1e30f; lrow[i] = 0.0f; }

    for (int t = 0; t < L_ / 64; ++t) {
        __syncthreads();   // prev iter done with KPs(P)/Vs; also fences Qs on t=0
        const float* kt = kb + (size_t)t * 64 * D_;
        const float* vt = vb + (size_t)t * 64 * D_;
#pragma unroll
        for (int it = 0; it < 4; ++it) {
            int idx = tid + it * 256;
            int r  = idx >> 4;
            int c4 = idx & 15;
            float4 kvv = *(const float4*)(kt + (size_t)r * D_ + c4 * 4);
            KPs[(c4 * 4 + 0) * 65 + r] = kvv.x;
            KPs[(c4 * 4 + 1) * 65 + r] = kvv.y;
            KPs[(c4 * 4 + 2) * 65 + r] = kvv.z;
            KPs[(c4 * 4 + 3) * 65 + r] = kvv.w;
            float4 vv = *(const float4*)(vt + (size_t)r * D_ + c4 * 4);
            *(float4*)&Vs[r * 64 + c4 * 4] = vv;
        }
        __syncthreads();

        // S = Q K^T  (4x4 per thread)
        float S[4][4];
#pragma unroll
        for (int i = 0; i < 4; ++i)
#pragma unroll
            for (int j = 0; j < 4; ++j) S[i][j] = 0.0f;
#pragma unroll 8
        for (int kk = 0; kk < 64; ++kk) {
            float qv[4], kv[4];
#pragma unroll
            for (int i = 0; i < 4; ++i) qv[i] = Qs[kk * 65 + ty * 4 + i];
#pragma unroll
            for (int j = 0; j < 4; ++j) kv[j] = KPs[kk * 65 + tx * 4 + j];
#pragma unroll
            for (int i = 0; i < 4; ++i)
#pragma unroll
                for (int j = 0; j < 4; ++j)
                    S[i][j] = fmaf(qv[i], kv[j], S[i][j]);
        }

        // Online softmax update (reduce across the 16 lanes sharing a row set)
#pragma unroll
        for (int i = 0; i < 4; ++i) {
            float rmax = fmaxf(fmaxf(S[i][0], S[i][1]), fmaxf(S[i][2], S[i][3]));
            rmax = fmaxf(rmax, __shfl_xor_sync(0xffffffffu, rmax, 1));
            rmax = fmaxf(rmax, __shfl_xor_sync(0xffffffffu, rmax, 2));
            rmax = fmaxf(rmax, __shfl_xor_sync(0xffffffffu, rmax, 4));
            rmax = fmaxf(rmax, __shfl_xor_sync(0xffffffffu, rmax, 8));
            float mnew = fmaxf(mrow[i], rmax);
            float corr = __expf(mrow[i] - mnew);
            mrow[i] = mnew;
            float rsum = 0.0f;
#pragma unroll
            for (int j = 0; j < 4; ++j) {
                S[i][j] = __expf(S[i][j] - mnew);
                rsum += S[i][j];
            }
            rsum += __shfl_xor_sync(0xffffffffu, rsum, 1);
            rsum += __shfl_xor_sync(0xffffffffu, rsum, 2);
            rsum += __shfl_xor_sync(0xffffffffu, rsum, 4);
            rsum += __shfl_xor_sync(0xffffffffu, rsum, 8);
            lrow[i] = lrow[i] * corr + rsum;
#pragma unroll
            for (int j = 0; j < 4; ++j) acc[i][j] *= corr;
        }

        __syncthreads();   // everyone done reading KPs as K
        // write P into KPs as [row][key], stride 65
#pragma unroll
        for (int i = 0; i < 4; ++i)
#pragma unroll
            for (int j = 0; j < 4; ++j)
                KPs[(ty * 4 + i) * 65 + tx * 4 + j] = S[i][j];
        __syncthreads();

        // O += P @ V
#pragma unroll 8
        for (int kk = 0; kk < 64; ++kk) {
            float4 vv = *(const float4*)&Vs[kk * 64 + tx * 4];
#pragma unroll
            for (int i = 0; i < 4; ++i) {
                float p = KPs[(ty * 4 + i) * 65 + kk];
                acc[i][0] = fmaf(p, vv.x, acc[i][0]);
                acc[i][1] = fmaf(p, vv.y, acc[i][1]);
                acc[i][2] = fmaf(p, vv.z, acc[i][2]);
                acc[i][3] = fmaf(p, vv.w, acc[i][3]);
            }
        }
    }

    // normalize and store
    float* ob = o + ((size_t)b * L_ + q0) * D_ + h * HD;
#pragma unroll
    for (int i = 0; i < 4; ++i) {
        float inv = 1.0f / lrow[i];
        float4 out = make_float4(acc[i][0] * inv, acc[i][1] * inv,
                                 acc[i][2] * inv, acc[i][3] * inv);
        *(float4*)(ob + (size_t)(ty * 4 + i) * D_ + tx * 4) = out;
    }
}

// ---------------------------------------------------------------------------
// Host launcher
// Inputs (metadata order): x [2,2048,1024] f32, Wq, Wk, Wv, Wo [1024,1024] f32,
// is_training (unused). Output: [2,2048,1024] f32.
// ---------------------------------------------------------------------------
extern "C" void kernel_launch(void* const* d_in, const int* in_sizes, int n_in,
                              void* d_out, int out_size)
{
    const float* x  = (const float*)d_in[0];
    const float* Wq = (const float*)d_in[1];
    const float* Wk = (const float*)d_in[2];
    const float* Wv = (const float*)d_in[3];
    const float* Wo = (const float*)d_in[4];
    float* out = (float*)d_out;

    float *qp, *kp, *vp, *yp;
    cudaGetSymbolAddress((void**)&qp, g_q);
    cudaGetSymbolAddress((void**)&kp, g_k);
    cudaGetSymbolAddress((void**)&vp, g_v);
    cudaGetSymbolAddress((void**)&yp, g_y);

    dim3 ggrid(D_ / 128, M_ / 128);   // (8, 32)
    const float qscale = 1.0f / 32.0f;  // 1/sqrt(1024)

    sgemm128<<<ggrid, 256>>>(x, Wq, qp, M_, D_, D_, qscale);
    sgemm128<<<ggrid, 256>>>(x, Wk, kp, M_, D_, D_, 1.0f);
    sgemm128<<<ggrid, 256>>>(x, Wv, vp, M_, D_, D_, 1.0f);

    rope_kernel<<<(M_ * (D_ / 2)) / 256, 256>>>(qp, kp);

    cudaFuncSetAttribute(flash_kernel,
                         cudaFuncAttributeMaxDynamicSharedMemorySize,
                         FA_SMEM_BYTES);
    dim3 fgrid(L_ / 64, H_, B_);      // (32, 16, 2)
    flash_kernel<<<fgrid, 256, FA_SMEM_BYTES>>>(qp, kp, vp, yp);

    sgemm128<<<ggrid, 256>>>(yp, Wo, out, M_, D_, D_, 1.0f);
}

// round 3
// speedup vs baseline: 1.3695x; 1.3695x over previous
#include <cuda_runtime.h>
#include <cuda_bf16.h>
#include <math.h>
#include <stdint.h>

// Problem constants
#define B_  2
#define L_  2048
#define D_  1024
#define H_  16
#define HD  64
#define M_  (B_ * L_)   // 4096

// ---------------------------------------------------------------------------
// Scratch (static device globals; no dynamic allocation allowed)
// ---------------------------------------------------------------------------
__device__ float g_q[M_ * D_];
__device__ float g_k[M_ * D_];
__device__ float g_v[M_ * D_];
__device__ float g_y[M_ * D_];
__device__ float g_wt[4][D_ * D_];   // transposed weights

// ---------------------------------------------------------------------------
// Weight transpose: g_wt[i] = W_i^T (B operand becomes [N,K], K contiguous)
// ---------------------------------------------------------------------------
__global__ __launch_bounds__(256) void transpose4(
    const float* __restrict__ W0, const float* __restrict__ W1,
    const float* __restrict__ W2, const float* __restrict__ W3)
{
    __shared__ float tile[32][33];
    const float* srcs[4] = {W0, W1, W2, W3};
    const float* src = srcs[blockIdx.z];
    float* dst = g_wt[blockIdx.z];

    int x = blockIdx.x * 32 + threadIdx.x;
    int y = blockIdx.y * 32 + threadIdx.y;
#pragma unroll
    for (int i = 0; i < 4; ++i)
        tile[threadIdx.y + i * 8][threadIdx.x] = src[(size_t)(y + i * 8) * D_ + x];
    __syncthreads();
    x = blockIdx.y * 32 + threadIdx.x;
    y = blockIdx.x * 32 + threadIdx.y;
#pragma unroll
    for (int i = 0; i < 4; ++i)
        dst[(size_t)(y + i * 8) * D_ + x] = tile[threadIdx.x][threadIdx.y + i * 8];
}

// ---------------------------------------------------------------------------
// mma.sync bf16 helper: D(16x8,f32) += A(16x16,bf16) * B(16x8,bf16)^T-ish
// (row.col: A row-major m x k, B given as n rows of k)
// ---------------------------------------------------------------------------
__device__ __forceinline__ void mma16816(float* c,
                                         uint32_t a0, uint32_t a1,
                                         uint32_t a2, uint32_t a3,
                                         uint32_t b0, uint32_t b1)
{
    asm volatile(
        "mma.sync.aligned.m16n8k16.row.col.f32.bf16.bf16.f32 "
        "{%0,%1,%2,%3}, {%4,%5,%6,%7}, {%8,%9}, {%0,%1,%2,%3};"
        : "+f"(c[0]), "+f"(c[1]), "+f"(c[2]), "+f"(c[3])
        : "r"(a0), "r"(a1), "r"(a2), "r"(a3), "r"(b0), "r"(b1));
}

// split a float pair into bf16 hi/lo packed registers
__device__ __forceinline__ void split2(float x0, float x1,
                                       uint32_t& hi, uint32_t& lo)
{
    __nv_bfloat16 h0 = __float2bfloat16(x0);
    __nv_bfloat16 h1 = __float2bfloat16(x1);
    __nv_bfloat16 l0 = __float2bfloat16(x0 - __bfloat162float(h0));
    __nv_bfloat16 l1 = __float2bfloat16(x1 - __bfloat162float(h1));
    __nv_bfloat162 hp = __nv_bfloat162(h0, h1);
    __nv_bfloat162 lp = __nv_bfloat162(l0, l1);
    hi = *(uint32_t*)&hp;
    lo = *(uint32_t*)&lp;
}

// ---------------------------------------------------------------------------
// bf16 3-term compensated tensor GEMM: C[M,N] = alpha * A[M,K] @ BT[N,K]^T
// CTA 128x128, K-chunk 32, 256 threads = 8 warps (2 m x 4 n), warp tile 64x32.
// Atom m16n8k16; 3 passes (AhBh + AlBh + AhBl) for ~fp32 accuracy.
// ---------------------------------------------------------------------------
#define GK 1024
#define GN 1024
#define AST 20   // row stride in bf16x2 units (32 data + pad) -> LDS conflict-free

__global__ __launch_bounds__(256) void gemm_bf16x3(
    const float* __restrict__ A, const float* __restrict__ BT,
    float* __restrict__ C, float alpha)
{
    __shared__ uint32_t Ah[128 * AST], Al[128 * AST];
    __shared__ uint32_t Bh[128 * AST], Bl[128 * AST];

    const int tid = threadIdx.x;
    const int wid = tid >> 5;
    const int lane = tid & 31;
    const int wm = wid & 1;        // 0..1  (m warp)
    const int wn = wid >> 1;       // 0..3  (n warp)
    const int g  = lane >> 2;      // 0..7
    const int t  = lane & 3;       // 0..3
    const int m0 = blockIdx.y * 128;
    const int n0 = blockIdx.x * 128;

    float acc[4][4][4];
#pragma unroll
    for (int i = 0; i < 4; ++i)
#pragma unroll
        for (int j = 0; j < 4; ++j)
#pragma unroll
            for (int r = 0; r < 4; ++r) acc[i][j][r] = 0.0f;

    const int ldr  = tid >> 3;       // 0..31 base row (x4 iters -> 128)
    const int ldc4 = tid & 7;        // float4 index within 32-k row

    for (int chunk = 0; chunk < GK / 32; ++chunk) {
        const int k0 = chunk * 32;
        __syncthreads();   // previous iteration's fragment reads done
#pragma unroll
        for (int it = 0; it < 4; ++it) {
            int r = ldr + it * 32;
            float4 a = *(const float4*)(A  + (size_t)(m0 + r) * GK + k0 + ldc4 * 4);
            float4 b = *(const float4*)(BT + (size_t)(n0 + r) * GK + k0 + ldc4 * 4);
            uint32_t h0, l0, h1, l1;
            split2(a.x, a.y, h0, l0);
            split2(a.z, a.w, h1, l1);
            Ah[r * AST + ldc4 * 2]     = h0;
            Ah[r * AST + ldc4 * 2 + 1] = h1;
            Al[r * AST + ldc4 * 2]     = l0;
            Al[r * AST + ldc4 * 2 + 1] = l1;
            split2(b.x, b.y, h0, l0);
            split2(b.z, b.w, h1, l1);
            Bh[r * AST + ldc4 * 2]     = h0;
            Bh[r * AST + ldc4 * 2 + 1] = h1;
            Bl[r * AST + ldc4 * 2]     = l0;
            Bl[r * AST + ldc4 * 2 + 1] = l1;
        }
        __syncthreads();

#pragma unroll
        for (int ks = 0; ks < 2; ++ks) {       // two k16 steps per chunk
            const int pc = ks * 8 + t;         // bf16x2 column within row
            // B fragments for all 4 n-atoms
            uint32_t bh[4][2], bl[4][2];
#pragma unroll
            for (int j = 0; j < 4; ++j) {
                int nr = wn * 32 + j * 8 + g;
                bh[j][0] = Bh[nr * AST + pc];
                bh[j][1] = Bh[nr * AST + pc + 4];
                bl[j][0] = Bl[nr * AST + pc];
                bl[j][1] = Bl[nr * AST + pc + 4];
            }
#pragma unroll
            for (int i = 0; i < 4; ++i) {
                int mr = wm * 64 + i * 16 + g;
                uint32_t ah0 = Ah[mr * AST + pc];
                uint32_t ah1 = Ah[(mr + 8) * AST + pc];
                uint32_t ah2 = Ah[mr * AST + pc + 4];
                uint32_t ah3 = Ah[(mr + 8) * AST + pc + 4];
                uint32_t al0 = Al[mr * AST + pc];
                uint32_t al1 = Al[(mr + 8) * AST + pc];
                uint32_t al2 = Al[mr * AST + pc + 4];
                uint32_t al3 = Al[(mr + 8) * AST + pc + 4];
#pragma unroll
                for (int j = 0; j < 4; ++j) {
                    mma16816(acc[i][j], ah0, ah1, ah2, ah3, bh[j][0], bh[j][1]);
                    mma16816(acc[i][j], al0, al1, al2, al3, bh[j][0], bh[j][1]);
                    mma16816(acc[i][j], ah0, ah1, ah2, ah3, bl[j][0], bl[j][1]);
                }
            }
        }
    }

    // Epilogue: c0,c1 -> (row, col..col+1); c2,c3 -> (row+8, ...)
#pragma unroll
    for (int i = 0; i < 4; ++i) {
        int row = m0 + wm * 64 + i * 16 + g;
#pragma unroll
        for (int j = 0; j < 4; ++j) {
            int col = n0 + wn * 32 + j * 8 + t * 2;
            float2 o0 = make_float2(alpha * acc[i][j][0], alpha * acc[i][j][1]);
            float2 o1 = make_float2(alpha * acc[i][j][2], alpha * acc[i][j][3]);
            *(float2*)(C + (size_t)row * GN + col)       = o0;
            *(float2*)(C + (size_t)(row + 8) * GN + col) = o1;
        }
    }
}

// ---------------------------------------------------------------------------
// RoPE applied in-place to q and k (layout [b*l][d], head = 64-col slice)
// ---------------------------------------------------------------------------
__global__ __launch_bounds__(256) void rope_kernel(float* __restrict__ q,
                                                   float* __restrict__ k)
{
    int idx = blockIdx.x * blockDim.x + threadIdx.x;   // < M_ * 512
    int row = idx >> 9;          // b*L + l
    int c   = idx & 511;
    int h   = c >> 5;            // head
    int i   = c & 31;            // pair index 0..31
    int pos = row & (L_ - 1);    // l

    float freq = exp2f(-13.287712379549449f * (float)(2 * i) * (1.0f / 64.0f));
    float ang  = (float)pos * freq;
    float s, cc;
    sincosf(ang, &s, &cc);

    int base = row * D_ + h * HD + 2 * i;
    float q0 = q[base], q1 = q[base + 1];
    q[base]     = q0 * cc - q1 * s;
    q[base + 1] = q1 * cc + q0 * s;
    float k0 = k[base], k1 = k[base + 1];
    k[base]     = k0 * cc - k1 * s;
    k[base + 1] = k1 * cc + k0 * s;
}

// ---------------------------------------------------------------------------
// Flash attention (fp32): per (b, h, q-tile of 64) block. (proven R1 kernel)
// ---------------------------------------------------------------------------
#define FA_SMEM_FLOATS (64 * 65 * 2 + 64 * 64)
#define FA_SMEM_BYTES  (FA_SMEM_FLOATS * 4)

__global__ __launch_bounds__(256) void flash_kernel(
    const float* __restrict__ q, const float* __restrict__ k,
    const float* __restrict__ v, float* __restrict__ o)
{
    extern __shared__ float smf[];
    float* Qs  = smf;
    float* KPs = smf + 64 * 65;
    float* Vs  = smf + 2 * 64 * 65;

    const int tid = threadIdx.x;
    const int ty = tid >> 4;
    const int tx = tid & 15;
    const int q0 = blockIdx.x * 64;
    const int h  = blockIdx.y;
    const int b  = blockIdx.z;

    const float* qb = q + ((size_t)b * L_ + q0) * D_ + h * HD;
    const float* kb = k + (size_t)b * L_ * D_ + h * HD;
    const float* vb = v + (size_t)b * L_ * D_ + h * HD;

#pragma unroll
    for (int it = 0; it < 4; ++it) {
        int idx = tid + it * 256;
        int r  = idx >> 4;
        int c4 = idx & 15;
        float4 val = *(const float4*)(qb + (size_t)r * D_ + c4 * 4);
        Qs[(c4 * 4 + 0) * 65 + r] = val.x;
        Qs[(c4 * 4 + 1) * 65 + r] = val.y;
        Qs[(c4 * 4 + 2) * 65 + r] = val.z;
        Qs[(c4 * 4 + 3) * 65 + r] = val.w;
    }

    float acc[4][4];
#pragma unroll
    for (int i = 0; i < 4; ++i)
#pragma unroll
        for (int j = 0; j < 4; ++j) acc[i][j] = 0.0f;
    float mrow[4], lrow[4];
#pragma unroll
    for (int i = 0; i < 4; ++i) { mrow[i] = -1e30f; lrow[i] = 0.0f; }

    for (int tile = 0; tile < L_ / 64; ++tile) {
        __syncthreads();
        const float* kt = kb + (size_t)tile * 64 * D_;
        const float* vt = vb + (size_t)tile * 64 * D_;
#pragma unroll
        for (int it = 0; it < 4; ++it) {
            int idx = tid + it * 256;
            int r  = idx >> 4;
            int c4 = idx & 15;
            float4 kvv = *(const float4*)(kt + (size_t)r * D_ + c4 * 4);
            KPs[(c4 * 4 + 0) * 65 + r] = kvv.x;
            KPs[(c4 * 4 + 1) * 65 + r] = kvv.y;
            KPs[(c4 * 4 + 2) * 65 + r] = kvv.z;
            KPs[(c4 * 4 + 3) * 65 + r] = kvv.w;
            float4 vv = *(const float4*)(vt + (size_t)r * D_ + c4 * 4);
            *(float4*)&Vs[r * 64 + c4 * 4] = vv;
        }
        __syncthreads();

        float S[4][4];
#pragma unroll
        for (int i = 0; i < 4; ++i)
#pragma unroll
            for (int j = 0; j < 4; ++j) S[i][j] = 0.0f;
#pragma unroll 8
        for (int kk = 0; kk < 64; ++kk) {
            float qv[4], kv[4];
#pragma unroll
            for (int i = 0; i < 4; ++i) qv[i] = Qs[kk * 65 + ty * 4 + i];
#pragma unroll
            for (int j = 0; j < 4; ++j) kv[j] = KPs[kk * 65 + tx * 4 + j];
#pragma unroll
            for (int i = 0; i < 4; ++i)
#pragma unroll
                for (int j = 0; j < 4; ++j)
                    S[i][j] = fmaf(qv[i], kv[j], S[i][j]);
        }

#pragma unroll
        for (int i = 0; i < 4; ++i) {
            float rmax = fmaxf(fmaxf(S[i][0], S[i][1]), fmaxf(S[i][2], S[i][3]));
            rmax = fmaxf(rmax, __shfl_xor_sync(0xffffffffu, rmax, 1));
            rmax = fmaxf(rmax, __shfl_xor_sync(0xffffffffu, rmax, 2));
            rmax = fmaxf(rmax, __shfl_xor_sync(0xffffffffu, rmax, 4));
            rmax = fmaxf(rmax, __shfl_xor_sync(0xffffffffu, rmax, 8));
            float mnew = fmaxf(mrow[i], rmax);
            float corr = __expf(mrow[i] - mnew);
            mrow[i] = mnew;
            float rsum = 0.0f;
#pragma unroll
            for (int j = 0; j < 4; ++j) {
                S[i][j] = __expf(S[i][j] - mnew);
                rsum += S[i][j];
            }
            rsum += __shfl_xor_sync(0xffffffffu, rsum, 1);
            rsum += __shfl_xor_sync(0xffffffffu, rsum, 2);
            rsum += __shfl_xor_sync(0xffffffffu, rsum, 4);
            rsum += __shfl_xor_sync(0xffffffffu, rsum, 8);
            lrow[i] = lrow[i] * corr + rsum;
#pragma unroll
            for (int j = 0; j < 4; ++j) acc[i][j] *= corr;
        }

        __syncthreads();
#pragma unroll
        for (int i = 0; i < 4; ++i)
#pragma unroll
            for (int j = 0; j < 4; ++j)
                KPs[(ty * 4 + i) * 65 + tx * 4 + j] = S[i][j];
        __syncthreads();

#pragma unroll 8
        for (int kk = 0; kk < 64; ++kk) {
            float4 vv = *(const float4*)&Vs[kk * 64 + tx * 4];
#pragma unroll
            for (int i = 0; i < 4; ++i) {
                float p = KPs[(ty * 4 + i) * 65 + kk];
                acc[i][0] = fmaf(p, vv.x, acc[i][0]);
                acc[i][1] = fmaf(p, vv.y, acc[i][1]);
                acc[i][2] = fmaf(p, vv.z, acc[i][2]);
                acc[i][3] = fmaf(p, vv.w, acc[i][3]);
            }
        }
    }

    float* ob = o + ((size_t)b * L_ + q0) * D_ + h * HD;
#pragma unroll
    for (int i = 0; i < 4; ++i) {
        float inv = 1.0f / lrow[i];
        float4 out = make_float4(acc[i][0] * inv, acc[i][1] * inv,
                                 acc[i][2] * inv, acc[i][3] * inv);
        *(float4*)(ob + (size_t)(ty * 4 + i) * D_ + tx * 4) = out;
    }
}

// ---------------------------------------------------------------------------
// Host launcher
// ---------------------------------------------------------------------------
extern "C" void kernel_launch(void* const* d_in, const int* in_sizes, int n_in,
                              void* d_out, int out_size)
{
    const float* x  = (const float*)d_in[0];
    const float* Wq = (const float*)d_in[1];
    const float* Wk = (const float*)d_in[2];
    const float* Wv = (const float*)d_in[3];
    const float* Wo = (const float*)d_in[4];
    float* out = (float*)d_out;

    float *qp, *kp, *vp, *yp, *wtp;
    cudaGetSymbolAddress((void**)&qp, g_q);
    cudaGetSymbolAddress((void**)&kp, g_k);
    cudaGetSymbolAddress((void**)&vp, g_v);
    cudaGetSymbolAddress((void**)&yp, g_y);
    cudaGetSymbolAddress((void**)&wtp, g_wt);

    // 1. Transpose the four weight matrices
    dim3 tgrid(D_ / 32, D_ / 32, 4);
    transpose4<<<tgrid, dim3(32, 8)>>>(Wq, Wk, Wv, Wo);

    // 2. QKV projections (tensor-core bf16 3-term)
    dim3 ggrid(GN / 128, M_ / 128);   // (8, 32)
    const float qscale = 1.0f / 32.0f;  // 1/sqrt(1024)
    gemm_bf16x3<<<ggrid, 256>>>(x, wtp + 0 * D_ * D_, qp, qscale);
    gemm_bf16x3<<<ggrid, 256>>>(x, wtp + 1 * D_ * D_, kp, 1.0f);
    gemm_bf16x3<<<ggrid, 256>>>(x, wtp + 2 * D_ * D_, vp, 1.0f);

    // 3. RoPE
    rope_kernel<<<(M_ * (D_ / 2)) / 256, 256>>>(qp, kp);

    // 4. Flash attention
    cudaFuncSetAttribute(flash_kernel,
                         cudaFuncAttributeMaxDynamicSharedMemorySize,
                         FA_SMEM_BYTES);
    dim3 fgrid(L_ / 64, H_, B_);      // (32, 16, 2)
    flash_kernel<<<fgrid, 256, FA_SMEM_BYTES>>>(qp, kp, vp, yp);

    // 5. Output projection
    gemm_bf16x3<<<ggrid, 256>>>(yp, wtp + 3 * D_ * D_, out, 1.0f);
}

// round 4
// speedup vs baseline: 2.4769x; 1.8086x over previous
#include <cuda_runtime.h>
#include <cuda_bf16.h>
#include <math.h>
#include <stdint.h>

// Problem constants
#define B_  2
#define L_  2048
#define D_  1024
#define H_  16
#define HD  64
#define M_  (B_ * L_)   // 4096

// ---------------------------------------------------------------------------
// Scratch (static device globals; no dynamic allocation allowed)
// ---------------------------------------------------------------------------
__device__ float g_q[M_ * D_];
__device__ float g_k[M_ * D_];
__device__ float g_v[M_ * D_];
__device__ float g_y[M_ * D_];
__device__ float g_wt[4][D_ * D_];   // transposed weights

// ---------------------------------------------------------------------------
// mma.sync bf16: D(16x8,f32) += A(16x16 row) * B(16x8 col)
// ---------------------------------------------------------------------------
__device__ __forceinline__ void mma16816(float* c,
                                         uint32_t a0, uint32_t a1,
                                         uint32_t a2, uint32_t a3,
                                         uint32_t b0, uint32_t b1)
{
    asm volatile(
        "mma.sync.aligned.m16n8k16.row.col.f32.bf16.bf16.f32 "
        "{%0,%1,%2,%3}, {%4,%5,%6,%7}, {%8,%9}, {%0,%1,%2,%3};"
        : "+f"(c[0]), "+f"(c[1]), "+f"(c[2]), "+f"(c[3])
        : "r"(a0), "r"(a1), "r"(a2), "r"(a3), "r"(b0), "r"(b1));
}

// split a float pair into packed bf16 hi/lo
__device__ __forceinline__ void split2(float x0, float x1,
                                       uint32_t& hi, uint32_t& lo)
{
    __nv_bfloat162 hp = __floats2bfloat162_rn(x0, x1);
    float2 hf = __bfloat1622float2(hp);
    __nv_bfloat162 lp = __floats2bfloat162_rn(x0 - hf.x, x1 - hf.y);
    hi = *(uint32_t*)&hp;
    lo = *(uint32_t*)&lp;
}

// ---------------------------------------------------------------------------
// Weight transpose: g_wt[i] = W_i^T
// ---------------------------------------------------------------------------
__global__ __launch_bounds__(256) void transpose4(
    const float* __restrict__ W0, const float* __restrict__ W1,
    const float* __restrict__ W2, const float* __restrict__ W3)
{
    __shared__ float tile[32][33];
    const float* srcs[4] = {W0, W1, W2, W3};
    const float* src = srcs[blockIdx.z];
    float* dst = g_wt[blockIdx.z];

    int x = blockIdx.x * 32 + threadIdx.x;
    int y = blockIdx.y * 32 + threadIdx.y;
#pragma unroll
    for (int i = 0; i < 4; ++i)
        tile[threadIdx.y + i * 8][threadIdx.x] = src[(size_t)(y + i * 8) * D_ + x];
    __syncthreads();
    x = blockIdx.y * 32 + threadIdx.x;
    y = blockIdx.x * 32 + threadIdx.y;
#pragma unroll
    for (int i = 0; i < 4; ++i)
        dst[(size_t)(y + i * 8) * D_ + x] = tile[threadIdx.x][threadIdx.y + i * 8];
}

// ---------------------------------------------------------------------------
// bf16 3-term tensor GEMM (proven R3): C[M,N] = alpha * A[M,K] @ BT[N,K]^T
// ---------------------------------------------------------------------------
#define GK 1024
#define GN 1024
#define AST 20

__global__ __launch_bounds__(256) void gemm_bf16x3(
    const float* __restrict__ A, const float* __restrict__ BT,
    float* __restrict__ C, float alpha)
{
    __shared__ uint32_t Ah[128 * AST], Al[128 * AST];
    __shared__ uint32_t Bh[128 * AST], Bl[128 * AST];

    const int tid = threadIdx.x;
    const int wid = tid >> 5;
    const int lane = tid & 31;
    const int wm = wid & 1;
    const int wn = wid >> 1;
    const int g  = lane >> 2;
    const int t  = lane & 3;
    const int m0 = blockIdx.y * 128;
    const int n0 = blockIdx.x * 128;

    float acc[4][4][4];
#pragma unroll
    for (int i = 0; i < 4; ++i)
#pragma unroll
        for (int j = 0; j < 4; ++j)
#pragma unroll
            for (int r = 0; r < 4; ++r) acc[i][j][r] = 0.0f;

    const int ldr  = tid >> 3;
    const int ldc4 = tid & 7;

    for (int chunk = 0; chunk < GK / 32; ++chunk) {
        const int k0 = chunk * 32;
        __syncthreads();
#pragma unroll
        for (int it = 0; it < 4; ++it) {
            int r = ldr + it * 32;
            float4 a = *(const float4*)(A  + (size_t)(m0 + r) * GK + k0 + ldc4 * 4);
            float4 b = *(const float4*)(BT + (size_t)(n0 + r) * GK + k0 + ldc4 * 4);
            uint32_t h0, l0, h1, l1;
            split2(a.x, a.y, h0, l0);
            split2(a.z, a.w, h1, l1);
            Ah[r * AST + ldc4 * 2]     = h0;
            Ah[r * AST + ldc4 * 2 + 1] = h1;
            Al[r * AST + ldc4 * 2]     = l0;
            Al[r * AST + ldc4 * 2 + 1] = l1;
            split2(b.x, b.y, h0, l0);
            split2(b.z, b.w, h1, l1);
            Bh[r * AST + ldc4 * 2]     = h0;
            Bh[r * AST + ldc4 * 2 + 1] = h1;
            Bl[r * AST + ldc4 * 2]     = l0;
            Bl[r * AST + ldc4 * 2 + 1] = l1;
        }
        __syncthreads();

#pragma unroll
        for (int ks = 0; ks < 2; ++ks) {
            const int pc = ks * 8 + t;
            uint32_t bh[4][2], bl[4][2];
#pragma unroll
            for (int j = 0; j < 4; ++j) {
                int nr = wn * 32 + j * 8 + g;
                bh[j][0] = Bh[nr * AST + pc];
                bh[j][1] = Bh[nr * AST + pc + 4];
                bl[j][0] = Bl[nr * AST + pc];
                bl[j][1] = Bl[nr * AST + pc + 4];
            }
#pragma unroll
            for (int i = 0; i < 4; ++i) {
                int mr = wm * 64 + i * 16 + g;
                uint32_t ah0 = Ah[mr * AST + pc];
                uint32_t ah1 = Ah[(mr + 8) * AST + pc];
                uint32_t ah2 = Ah[mr * AST + pc + 4];
                uint32_t ah3 = Ah[(mr + 8) * AST + pc + 4];
                uint32_t al0 = Al[mr * AST + pc];
                uint32_t al1 = Al[(mr + 8) * AST + pc];
                uint32_t al2 = Al[mr * AST + pc + 4];
                uint32_t al3 = Al[(mr + 8) * AST + pc + 4];
#pragma unroll
                for (int j = 0; j < 4; ++j) {
                    mma16816(acc[i][j], ah0, ah1, ah2, ah3, bh[j][0], bh[j][1]);
                    mma16816(acc[i][j], al0, al1, al2, al3, bh[j][0], bh[j][1]);
                    mma16816(acc[i][j], ah0, ah1, ah2, ah3, bl[j][0], bl[j][1]);
                }
            }
        }
    }

#pragma unroll
    for (int i = 0; i < 4; ++i) {
        int row = m0 + wm * 64 + i * 16 + g;
#pragma unroll
        for (int j = 0; j < 4; ++j) {
            int col = n0 + wn * 32 + j * 8 + t * 2;
            float2 o0 = make_float2(alpha * acc[i][j][0], alpha * acc[i][j][1]);
            float2 o1 = make_float2(alpha * acc[i][j][2], alpha * acc[i][j][3]);
            *(float2*)(C + (size_t)row * GN + col)       = o0;
            *(float2*)(C + (size_t)(row + 8) * GN + col) = o1;
        }
    }
}

// ---------------------------------------------------------------------------
// RoPE applied in-place to q and k
// ---------------------------------------------------------------------------
__global__ __launch_bounds__(256) void rope_kernel(float* __restrict__ q,
                                                   float* __restrict__ k)
{
    int idx = blockIdx.x * blockDim.x + threadIdx.x;
    int row = idx >> 9;
    int c   = idx & 511;
    int h   = c >> 5;
    int i   = c & 31;
    int pos = row & (L_ - 1);

    float freq = exp2f(-13.287712379549449f * (float)(2 * i) * (1.0f / 64.0f));
    float ang  = (float)pos * freq;
    float s, cc;
    sincosf(ang, &s, &cc);

    int base = row * D_ + h * HD + 2 * i;
    float q0 = q[base], q1 = q[base + 1];
    q[base]     = q0 * cc - q1 * s;
    q[base + 1] = q1 * cc + q0 * s;
    float k0 = k[base], k1 = k[base + 1];
    k[base]     = k0 * cc - k1 * s;
    k[base + 1] = k1 * cc + k0 * s;
}

// ---------------------------------------------------------------------------
// Tensor-core flash attention.
// CTA: 128 q-rows (8 warps x 16 rows) for one (b,h); key tiles of 64.
// S = QK^T via 3-term bf16 mma; P reused directly from S C-fragments
// (C frag == A frag layout); PV via 3-term as well.
// K/V in smem as bf16x2, row stride 36 u32 -> conflict-free fragment loads.
// ---------------------------------------------------------------------------
#define FST 36   // smem row stride (u32 units)

__global__ __launch_bounds__(256, 2) void flash_mma(
    const float* __restrict__ q, const float* __restrict__ k,
    const float* __restrict__ v, float* __restrict__ o)
{
    __shared__ uint32_t Khi[64 * FST], Klo[64 * FST];
    __shared__ uint32_t Vhi[64 * FST], Vlo[64 * FST];

    const int tid  = threadIdx.x;
    const int wid  = tid >> 5;
    const int lane = tid & 31;
    const int g = lane >> 2;      // 0..7
    const int t = lane & 3;       // 0..3
    const int q0 = blockIdx.x * 128;
    const int h  = blockIdx.y;
    const int b  = blockIdx.z;

    const float* kb = k + (size_t)b * L_ * D_ + h * HD;
    const float* vb = v + (size_t)b * L_ * D_ + h * HD;

    // ---- Load this warp's Q fragments (rows wid*16 + g / +8), hi/lo split.
    uint32_t qh[4][4], ql[4][4];
    {
        const float* qrow0 = q + ((size_t)b * L_ + q0 + wid * 16 + g) * D_ + h * HD;
        const float* qrow1 = qrow0 + 8 * D_;
#pragma unroll
        for (int ks = 0; ks < 4; ++ks) {
            float2 x0 = *(const float2*)(qrow0 + ks * 16 + 2 * t);
            float2 x1 = *(const float2*)(qrow1 + ks * 16 + 2 * t);
            float2 x2 = *(const float2*)(qrow0 + ks * 16 + 2 * t + 8);
            float2 x3 = *(const float2*)(qrow1 + ks * 16 + 2 * t + 8);
            split2(x0.x, x0.y, qh[ks][0], ql[ks][0]);
            split2(x1.x, x1.y, qh[ks][1], ql[ks][1]);
            split2(x2.x, x2.y, qh[ks][2], ql[ks][2]);
            split2(x3.x, x3.y, qh[ks][3], ql[ks][3]);
        }
    }

    float acc[8][4];
#pragma unroll
    for (int j = 0; j < 8; ++j)
#pragma unroll
        for (int r = 0; r < 4; ++r) acc[j][r] = 0.0f;
    float m0r = -1e30f, m1r = -1e30f, l0r = 0.0f, l1r = 0.0f;

    for (int tile = 0; tile < L_ / 64; ++tile) {
        __syncthreads();   // previous tile's fragment reads done
        // ---- K tile: Kt[key][hd-pair]  (64 keys x 32 pairs)
        const float* kt = kb + (size_t)tile * 64 * D_;
#pragma unroll
        for (int i = 0; i < 4; ++i) {
            int idx = tid + i * 256;       // 0..1023
            int key = idx >> 4;
            int c4  = idx & 15;
            float4 x = *(const float4*)(kt + (size_t)key * D_ + c4 * 4);
            uint32_t h0, l0, h1, l1;
            split2(x.x, x.y, h0, l0);
            split2(x.z, x.w, h1, l1);
            Khi[key * FST + c4 * 2]     = h0;
            Khi[key * FST + c4 * 2 + 1] = h1;
            Klo[key * FST + c4 * 2]     = l0;
            Klo[key * FST + c4 * 2 + 1] = l1;
        }
        // ---- V tile transposed: Vt[hd][key-pair] (64 hd x 32 pairs)
        const float* vt = vb + (size_t)tile * 64 * D_;
#pragma unroll
        for (int i = 0; i < 2; ++i) {
            int idx = tid + i * 256;       // 0..511
            int c4 = idx & 15;
            int kp = idx >> 4;             // 0..31
            float4 v0 = *(const float4*)(vt + (size_t)(2 * kp) * D_ + c4 * 4);
            float4 v1 = *(const float4*)(vt + (size_t)(2 * kp + 1) * D_ + c4 * 4);
            const float* p0 = (const float*)&v0;
            const float* p1 = (const float*)&v1;
#pragma unroll
            for (int cc = 0; cc < 4; ++cc) {
                uint32_t hi, lo;
                split2(p0[cc], p1[cc], hi, lo);
                Vhi[(c4 * 4 + cc) * FST + kp] = hi;
                Vlo[(c4 * 4 + cc) * FST + kp] = lo;
            }
        }
        __syncthreads();

        // ---- S = Q K^T  (8 key atoms x 4 k-steps x 3 passes)
        float S[8][4];
#pragma unroll
        for (int j = 0; j < 8; ++j)
#pragma unroll
            for (int r = 0; r < 4; ++r) S[j][r] = 0.0f;
#pragma unroll
        for (int j = 0; j < 8; ++j) {
            const int nr = j * 8 + g;
#pragma unroll
            for (int ks = 0; ks < 4; ++ks) {
                uint32_t bh0 = Khi[nr * FST + ks * 8 + t];
                uint32_t bh1 = Khi[nr * FST + ks * 8 + t + 4];
                uint32_t bl0 = Klo[nr * FST + ks * 8 + t];
                uint32_t bl1 = Klo[nr * FST + ks * 8 + t + 4];
                mma16816(S[j], qh[ks][0], qh[ks][1], qh[ks][2], qh[ks][3], bh0, bh1);
                mma16816(S[j], ql[ks][0], ql[ks][1], ql[ks][2], ql[ks][3], bh0, bh1);
                mma16816(S[j], qh[ks][0], qh[ks][1], qh[ks][2], qh[ks][3], bl0, bl1);
            }
        }

        // ---- Online softmax (rows g and g+8; reduce across quad t)
        float mx0 = -1e30f, mx1 = -1e30f;
#pragma unroll
        for (int j = 0; j < 8; ++j) {
            mx0 = fmaxf(mx0, fmaxf(S[j][0], S[j][1]));
            mx1 = fmaxf(mx1, fmaxf(S[j][2], S[j][3]));
        }
        mx0 = fmaxf(mx0, __shfl_xor_sync(0xffffffffu, mx0, 1));
        mx0 = fmaxf(mx0, __shfl_xor_sync(0xffffffffu, mx0, 2));
        mx1 = fmaxf(mx1, __shfl_xor_sync(0xffffffffu, mx1, 1));
        mx1 = fmaxf(mx1, __shfl_xor_sync(0xffffffffu, mx1, 2));

        float mn0 = fmaxf(m0r, mx0);
        float mn1 = fmaxf(m1r, mx1);
        float cr0 = __expf(m0r - mn0);
        float cr1 = __expf(m1r - mn1);
        m0r = mn0; m1r = mn1;

        float sum0 = 0.0f, sum1 = 0.0f;
#pragma unroll
        for (int j = 0; j < 8; ++j) {
            S[j][0] = __expf(S[j][0] - mn0);
            S[j][1] = __expf(S[j][1] - mn0);
            S[j][2] = __expf(S[j][2] - mn1);
            S[j][3] = __expf(S[j][3] - mn1);
            sum0 += S[j][0] + S[j][1];
            sum1 += S[j][2] + S[j][3];
        }
        sum0 += __shfl_xor_sync(0xffffffffu, sum0, 1);
        sum0 += __shfl_xor_sync(0xffffffffu, sum0, 2);
        sum1 += __shfl_xor_sync(0xffffffffu, sum1, 1);
        sum1 += __shfl_xor_sync(0xffffffffu, sum1, 2);
        l0r = l0r * cr0 + sum0;
        l1r = l1r * cr1 + sum1;
#pragma unroll
        for (int j = 0; j < 8; ++j) {
            acc[j][0] *= cr0;
            acc[j][1] *= cr0;
            acc[j][2] *= cr1;
            acc[j][3] *= cr1;
        }

        // ---- O += P V  (P fragments straight from S fragments; 3-term)
#pragma unroll
        for (int kb2 = 0; kb2 < 4; ++kb2) {
            uint32_t ph[4], pl[4];
            split2(S[2 * kb2][0],     S[2 * kb2][1],     ph[0], pl[0]);
            split2(S[2 * kb2][2],     S[2 * kb2][3],     ph[1], pl[1]);
            split2(S[2 * kb2 + 1][0], S[2 * kb2 + 1][1], ph[2], pl[2]);
            split2(S[2 * kb2 + 1][2], S[2 * kb2 + 1][3], ph[3], pl[3]);
#pragma unroll
            for (int j = 0; j < 8; ++j) {
                const int vr = j * 8 + g;
                uint32_t bh0 = Vhi[vr * FST + kb2 * 8 + t];
                uint32_t bh1 = Vhi[vr * FST + kb2 * 8 + t + 4];
                uint32_t bl0 = Vlo[vr * FST + kb2 * 8 + t];
                uint32_t bl1 = Vlo[vr * FST + kb2 * 8 + t + 4];
                mma16816(acc[j], ph[0], ph[1], ph[2], ph[3], bh0, bh1);
                mma16816(acc[j], pl[0], pl[1], pl[2], pl[3], bh0, bh1);
                mma16816(acc[j], ph[0], ph[1], ph[2], ph[3], bl0, bl1);
            }
        }
    }

    // ---- Normalize and store
    float inv0 = 1.0f / l0r;
    float inv1 = 1.0f / l1r;
    int row0 = q0 + wid * 16 + g;
    float* ob = o + ((size_t)b * L_ + row0) * D_ + h * HD;
#pragma unroll
    for (int j = 0; j < 8; ++j) {
        float2 o0 = make_float2(acc[j][0] * inv0, acc[j][1] * inv0);
        float2 o1 = make_float2(acc[j][2] * inv1, acc[j][3] * inv1);
        *(float2*)(ob + j * 8 + 2 * t)            = o0;
        *(float2*)(ob + 8 * D_ + j * 8 + 2 * t)   = o1;
    }
}

// ---------------------------------------------------------------------------
// Host launcher
// ---------------------------------------------------------------------------
extern "C" void kernel_launch(void* const* d_in, const int* in_sizes, int n_in,
                              void* d_out, int out_size)
{
    const float* x  = (const float*)d_in[0];
    const float* Wq = (const float*)d_in[1];
    const float* Wk = (const float*)d_in[2];
    const float* Wv = (const float*)d_in[3];
    const float* Wo = (const float*)d_in[4];
    float* out = (float*)d_out;

    float *qp, *kp, *vp, *yp, *wtp;
    cudaGetSymbolAddress((void**)&qp, g_q);
    cudaGetSymbolAddress((void**)&kp, g_k);
    cudaGetSymbolAddress((void**)&vp, g_v);
    cudaGetSymbolAddress((void**)&yp, g_y);
    cudaGetSymbolAddress((void**)&wtp, g_wt);

    // 1. Transpose the four weight matrices
    dim3 tgrid(D_ / 32, D_ / 32, 4);
    transpose4<<<tgrid, dim3(32, 8)>>>(Wq, Wk, Wv, Wo);

    // 2. QKV projections (tensor-core bf16 3-term)
    dim3 ggrid(GN / 128, M_ / 128);
    const float qscale = 1.0f / 32.0f;
    gemm_bf16x3<<<ggrid, 256>>>(x, wtp + 0 * D_ * D_, qp, qscale);
    gemm_bf16x3<<<ggrid, 256>>>(x, wtp + 1 * D_ * D_, kp, 1.0f);
    gemm_bf16x3<<<ggrid, 256>>>(x, wtp + 2 * D_ * D_, vp, 1.0f);

    // 3. RoPE
    rope_kernel<<<(M_ * (D_ / 2)) / 256, 256>>>(qp, kp);

    // 4. Tensor-core flash attention
    dim3 fgrid(L_ / 128, H_, B_);     // (16, 16, 2)
    flash_mma<<<fgrid, 256>>>(qp, kp, vp, yp);

    // 5. Output projection
    gemm_bf16x3<<<ggrid, 256>>>(yp, wtp + 3 * D_ * D_, out, 1.0f);
}